// round 14
// baseline (speedup 1.0000x reference)
#include <cuda_runtime.h>

#define BB 1024
#define DD 256
#define HH 32

// Column tables: exp(+W)/exp(-W) interleaved by j-pair, [16][DD] float2 — coalesced
// across k.  Row tables: [DD][HH] — coalesced across j for the rank-1 gather.
__device__ float  g_ewp[HH * DD];
__device__ float  g_ewm[HH * DD];
__device__ float  g_ewpR[DD * HH];
__device__ float  g_ewmR[DD * HH];
__device__ float2 g_eb[DD];          // (exp(+b/2), exp(-b/2))
__device__ float  g_E[BB * HH];      // E_j(row) = exp((x@W)_j + c_j)

// Prep: blocks 0..7 build tables; blocks 8..8+BB/8-1 compute E, 8 rows per block.
__global__ __launch_bounds__(256) void prep_kernel(
    const float* __restrict__ x,
    const float* __restrict__ W,
    const float* __restrict__ b,
    const float* __restrict__ c)
{
    const int bid = blockIdx.x;
    const int tid = threadIdx.x;
    if (bid < 8) {
        for (int t = bid * 256 + tid; t < DD * HH; t += 8 * 256) {
            int d = t >> 5;
            int j = t & 31;
            float w  = W[t];
            float ep = expf(w);
            float em = expf(-w);
            int idx = (j >> 1) * (DD * 2) + d * 2 + (j & 1);
            g_ewp[idx] = ep;
            g_ewm[idx] = em;
            g_ewpR[t] = ep;
            g_ewmR[t] = em;
        }
        int t = bid * 256 + tid;
        if (t < DD) {
            float bv = b[t];
            g_eb[t] = make_float2(expf(0.5f * bv), expf(-0.5f * bv));
        }
        cudaTriggerProgrammaticLaunchCompletion();
        return;
    }

    __shared__ float ap[8][8][32];           // [warp][row][j]
    const int row0 = (bid - 8) * 8;
    const int w    = tid >> 5;
    const int lane = tid & 31;

    unsigned m[8];
    #pragma unroll
    for (int r = 0; r < 8; ++r)
        m[r] = __ballot_sync(0xffffffffu, x[(row0 + r) * DD + w * 32 + lane] != 0.0f);

    const float* Wb = W + (w * 32) * HH + lane;
    float acc[8] = {0.f, 0.f, 0.f, 0.f, 0.f, 0.f, 0.f, 0.f};
    #pragma unroll
    for (int i = 0; i < 32; ++i) {
        float wv = Wb[i * HH];
        #pragma unroll
        for (int r = 0; r < 8; ++r)
            if (m[r] & (1u << i)) acc[r] += wv;
    }
    #pragma unroll
    for (int r = 0; r < 8; ++r) ap[w][r][lane] = acc[r];
    __syncthreads();

    float a = c[lane];
    #pragma unroll
    for (int ww = 0; ww < 8; ++ww) a += ap[ww][w][lane];
    g_E[(row0 + w) * HH + lane] = expf(a);
    cudaTriggerProgrammaticLaunchCompletion();
}

__device__ __forceinline__ unsigned fmono(float f) {
    unsigned u = __float_as_uint(f);
    return (u & 0x80000000u) ? ~u : (u | 0x80000000u);
}

// 256 threads, 1 dim/thread. Forward caches t_j = E_j * e^{delta_k w_kj} in
// registers; reverse pass is LDG-free: factor = 1 + t_j * m_j  (m = E'/E),
// except thread kstar whose factor is 1 + E_j (flip cancels m).
__global__ __launch_bounds__(256) void gwg_kernel(
    const float* __restrict__ x,
    const float* __restrict__ gum,
    const float* __restrict__ acc,
    float* __restrict__ out)
{
    __shared__ float xs[DD];
    __shared__ __align__(16) float sEf[8][HH];   // per-warp copy of E_j
    __shared__ __align__(16) float sM [8][HH];   // per-warp copy of m_j = E'_j/E_j
    __shared__ float sredf[8];
    __shared__ uint2 sredk[8];

    const int row  = blockIdx.x;
    const int tid  = threadIdx.x;
    const int w    = tid >> 5;
    const int lane = tid & 31;
    const int k    = tid;

    // prep-independent front work (overlaps prep via PDL)
    float xk = x[row * DD + k];
    float u  = gum[row * DD + k];
    float au = acc[row];
    xs[k] = xk;
    float z = -logf(u + 1e-9f) + 1e-9f;

    cudaGridDependencySynchronize();

    float2 ebv = g_eb[k];
    float E = g_E[row * HH + lane];
    sEf[w][lane] = E;
    __syncwarp();

    // ---- forward: t_j = E_j e^{delta w}; p = prod (1+t_j); ek = eb*sqrt(p) ----
    const float2* t0 = (const float2*)((xk == 0.0f) ? g_ewp : g_ewm);
    const float   eb = (xk == 0.0f) ? ebv.x : ebv.y;
    const float4* E4 = (const float4*)sEf[w];

    float2 t[16];
    float p0 = 1.f, p1 = 1.f, p2 = 1.f, p3 = 1.f;
    #pragma unroll
    for (int jp = 0; jp < 16; jp += 2) {
        float4 Ev = E4[jp >> 1];
        float2 eA = __ldg(&t0[jp * DD + k]);
        float2 eB = __ldg(&t0[(jp + 1) * DD + k]);
        t[jp].x     = Ev.x * eA.x;
        t[jp].y     = Ev.y * eA.y;
        t[jp + 1].x = Ev.z * eB.x;
        t[jp + 1].y = Ev.w * eB.y;
        p0 = fmaf(t[jp].x,     p0, p0);
        p1 = fmaf(t[jp].y,     p1, p1);
        p2 = fmaf(t[jp + 1].x, p2, p2);
        p3 = fmaf(t[jp + 1].y, p3, p3);
    }
    float ek  = eb * sqrtf((p0 * p1) * (p2 * p3));
    float key = ek / z;

    // warp sum + warp argmax
    float s = ek;
    #pragma unroll
    for (int off = 16; off; off >>= 1) s += __shfl_xor_sync(0xffffffffu, s, off);
    unsigned km   = fmono(key);
    unsigned wmax = __reduce_max_sync(0xffffffffu, km);
    unsigned ball = __ballot_sync(0xffffffffu, km == wmax);
    int      wki  = w * 32 + (__ffs(ball) - 1);
    if (lane == 0) { sredf[w] = s; sredk[w] = make_uint2(wmax, (unsigned)wki); }
    __syncthreads();                           // B2 (genuine combine)

    // ---- combine 8 warp partials via broadcast LDS ----
    float Sf;
    int   kstar;
    {
        Sf = ((sredf[0] + sredf[1]) + (sredf[2] + sredf[3]))
           + ((sredf[4] + sredf[5]) + (sredf[6] + sredf[7]));
        uint2 c0 = sredk[0], c1 = sredk[1], c2 = sredk[2], c3 = sredk[3];
        uint2 c4 = sredk[4], c5 = sredk[5], c6 = sredk[6], c7 = sredk[7];
        uint2 mA = (c1.x > c0.x) ? c1 : c0;
        uint2 mB = (c3.x > c2.x) ? c3 : c2;
        uint2 mC = (c5.x > c4.x) ? c5 : c4;
        uint2 mD = (c7.x > c6.x) ? c7 : c6;
        uint2 mAB = (mB.x > mA.x || (mB.x == mA.x && mB.y < mA.y)) ? mB : mA;
        uint2 mCD = (mD.x > mC.x || (mD.x == mC.x && mD.y < mC.y)) ? mD : mC;
        uint2 mm  = (mCD.x > mAB.x || (mCD.x == mAB.x && mCD.y < mAB.y)) ? mCD : mAB;
        kstar = (int)mm.y;
    }

    // ---- rank-1 multipliers m_j, per-warp redundant; acceptance ratio R ----
    float Rt;
    {
        float xks = xs[kstar];                 // written pre-B2
        const float* rowt = (xks == 0.0f) ? g_ewpR : g_ewmR;
        float mj  = __ldg(&rowt[kstar * HH + lane]);
        sM[w][lane] = mj;
        float E2  = E * mj;
        float rr  = (1.f + E2) / (1.f + E);
        #pragma unroll
        for (int off = 16; off; off >>= 1) rr *= __shfl_xor_sync(0xffffffffu, rr, off);
        Rt = rr;
        __syncwarp();
    }

    // ---- reverse: LDG-free. factor = 1 + t_j*m_j  (k != kstar) ----
    const bool  isks = (k == kstar);
    const float eb2  = isks ? ((xk == 0.0f) ? ebv.y : ebv.x) : eb;
    const float4* M4 = (const float4*)sM[w];

    float q0 = 1.f, q1 = 1.f, q2 = 1.f, q3 = 1.f;
    #pragma unroll
    for (int jp = 0; jp < 16; jp += 2) {
        float4 Mv = M4[jp >> 1];
        float u0 = t[jp].x     * Mv.x;
        float u1 = t[jp].y     * Mv.y;
        float u2 = t[jp + 1].x * Mv.z;
        float u3 = t[jp + 1].y * Mv.w;
        q0 = fmaf(u0, q0, q0);
        q1 = fmaf(u1, q1, q1);
        q2 = fmaf(u2, q2, q2);
        q3 = fmaf(u3, q3, q3);
    }
    // patch for the kstar thread: its true factors are (1 + E_j)
    if (isks) {
        q0 = 1.f; q1 = 1.f; q2 = 1.f; q3 = 1.f;
        #pragma unroll
        for (int jq = 0; jq < 8; ++jq) {
            float4 Ev = E4[jq];
            q0 = fmaf(Ev.x, q0, q0);
            q1 = fmaf(Ev.y, q1, q1);
            q2 = fmaf(Ev.z, q2, q2);
            q3 = fmaf(Ev.w, q3, q3);
        }
    }
    float ek2 = eb2 * sqrtf((q0 * q1) * (q2 * q3));

    float s2 = ek2;
    #pragma unroll
    for (int off = 16; off; off >>= 1) s2 += __shfl_xor_sync(0xffffffffu, s2, off);
    if (lane == 0) sredf[w] = s2;
    __syncthreads();                           // B4 (genuine combine)

    float Sr = ((sredf[0] + sredf[1]) + (sredf[2] + sredf[3]))
             + ((sredf[4] + sredf[5]) + (sredf[6] + sredf[7]));

    // ---- accept: Zf/Zr = sqrt(R) * Sf / Sr > u ----
    bool accv = sqrtf(Rt) * Sf > au * Sr;
    out[row * DD + k] = (isks && accv) ? (1.f - xk) : xk;
}

extern "C" void kernel_launch(void* const* d_in, const int* in_sizes, int n_in,
                              void* d_out, int out_size) {
    const float* x   = (const float*)d_in[0];
    const float* W   = (const float*)d_in[1];
    const float* b   = (const float*)d_in[2];
    const float* c   = (const float*)d_in[3];
    const float* gum = (const float*)d_in[4];
    const float* acc = (const float*)d_in[5];
    float* out = (float*)d_out;

    prep_kernel<<<8 + BB / 8, 256>>>(x, W, b, c);

    cudaLaunchConfig_t cfg = {};
    cfg.gridDim  = dim3(BB, 1, 1);
    cfg.blockDim = dim3(256, 1, 1);
    cfg.dynamicSmemBytes = 0;
    cfg.stream = 0;
    cudaLaunchAttribute attrs[1];
    attrs[0].id = cudaLaunchAttributeProgrammaticStreamSerialization;
    attrs[0].val.programmaticStreamSerializationAllowed = 1;
    cfg.attrs = attrs;
    cfg.numAttrs = 1;
    cudaLaunchKernelEx(&cfg, gwg_kernel, x, gum, acc, out);
}

// round 15
// speedup vs baseline: 1.1532x; 1.1532x over previous
#include <cuda_runtime.h>

#define BB 1024
#define DD 256
#define HH 32

#define ONE2 0x3F8000003F800000ULL

// packed f32x2 ops (Blackwell): 2 lanes per instruction
#define FMA2(d, a, b, c) asm("fma.rn.f32x2 %0, %1, %2, %3;" : "=l"(d) : "l"(a), "l"(b), "l"(c))
#define MUL2(d, a, b)    asm("mul.rn.f32x2 %0, %1, %2;"     : "=l"(d) : "l"(a), "l"(b))

__device__ __forceinline__ unsigned long long ldg2(const float2* p) {
    return __ldg((const unsigned long long*)p);
}
__device__ __forceinline__ float2 unpack2(unsigned long long v) {
    float2 r;
    asm("mov.b64 {%0, %1}, %2;" : "=f"(r.x), "=f"(r.y) : "l"(v));
    return r;
}

// Column tables: exp(+W)/exp(-W) interleaved by j-pair, [16][DD] float2 — coalesced
// across k.  Row tables: [DD][HH] — coalesced across j for the rank-1 gather.
__device__ float  g_ewp[HH * DD];
__device__ float  g_ewm[HH * DD];
__device__ float  g_ewpR[DD * HH];
__device__ float  g_ewmR[DD * HH];
__device__ float2 g_eb[DD];          // (exp(+b/2), exp(-b/2))
__device__ float  g_E[BB * HH];      // E_j(row) = exp((x@W)_j + c_j)

// Prep: blocks 0..7 build tables; blocks 8..8+BB/8-1 compute E, 8 rows per block.
__global__ __launch_bounds__(256) void prep_kernel(
    const float* __restrict__ x,
    const float* __restrict__ W,
    const float* __restrict__ b,
    const float* __restrict__ c)
{
    const int bid = blockIdx.x;
    const int tid = threadIdx.x;
    if (bid < 8) {
        for (int t = bid * 256 + tid; t < DD * HH; t += 8 * 256) {
            int d = t >> 5;
            int j = t & 31;
            float w  = W[t];
            float ep = expf(w);
            float em = expf(-w);
            int idx = (j >> 1) * (DD * 2) + d * 2 + (j & 1);
            g_ewp[idx] = ep;
            g_ewm[idx] = em;
            g_ewpR[t] = ep;
            g_ewmR[t] = em;
        }
        int t = bid * 256 + tid;
        if (t < DD) {
            float bv = b[t];
            g_eb[t] = make_float2(expf(0.5f * bv), expf(-0.5f * bv));
        }
        cudaTriggerProgrammaticLaunchCompletion();
        return;
    }

    __shared__ float ap[8][8][32];           // [warp][row][j]
    const int row0 = (bid - 8) * 8;
    const int w    = tid >> 5;
    const int lane = tid & 31;

    unsigned m[8];
    #pragma unroll
    for (int r = 0; r < 8; ++r)
        m[r] = __ballot_sync(0xffffffffu, x[(row0 + r) * DD + w * 32 + lane] != 0.0f);

    const float* Wb = W + (w * 32) * HH + lane;
    float acc[8] = {0.f, 0.f, 0.f, 0.f, 0.f, 0.f, 0.f, 0.f};
    #pragma unroll
    for (int i = 0; i < 32; ++i) {
        float wv = Wb[i * HH];
        #pragma unroll
        for (int r = 0; r < 8; ++r)
            if (m[r] & (1u << i)) acc[r] += wv;
    }
    #pragma unroll
    for (int r = 0; r < 8; ++r) ap[w][r][lane] = acc[r];
    __syncthreads();

    float a = c[lane];
    #pragma unroll
    for (int ww = 0; ww < 8; ++ww) a += ap[ww][w][lane];
    g_E[(row0 + w) * HH + lane] = expf(a);
    cudaTriggerProgrammaticLaunchCompletion();
}

__device__ __forceinline__ unsigned fmono(float f) {
    unsigned u = __float_as_uint(f);
    return (u & 0x80000000u) ? ~u : (u | 0x80000000u);
}

// R10 structure: 128 threads, 2 dims/thread, grid 1024, PDL; hot loops in f32x2.
__global__ __launch_bounds__(128, 8) void gwg_kernel(
    const float* __restrict__ x,
    const float* __restrict__ gum,
    const float* __restrict__ acc,
    float* __restrict__ out)
{
    __shared__ float xs[DD];
    __shared__ __align__(16) float sEf[4][HH];   // per-warp copy of E_j
    __shared__ __align__(16) float sE2[4][HH];   // per-warp copy of E'_j
    __shared__ float sredf[4];
    __shared__ uint2 sredk[4];                   // (fmono(key), idx) per warp

    const int row  = blockIdx.x;
    const int tid  = threadIdx.x;
    const int w    = tid >> 5;
    const int lane = tid & 31;
    const int k0   = tid;          // dims tid and tid+128
    const int k1   = tid + 128;

    // prep-independent front work (overlaps prep via PDL)
    float xk0 = x[row * DD + k0];
    float xk1 = x[row * DD + k1];
    float u0  = gum[row * DD + k0];
    float u1  = gum[row * DD + k1];
    float au  = acc[row];
    xs[k0] = xk0;
    xs[k1] = xk1;
    float z0 = -logf(u0 + 1e-9f) + 1e-9f;
    float z1 = -logf(u1 + 1e-9f) + 1e-9f;

    cudaGridDependencySynchronize();

    float2 eb0 = g_eb[k0];
    float2 eb1 = g_eb[k1];

    // each warp keeps its own E copy -> no cross-warp wait
    float E = g_E[row * HH + lane];
    sEf[w][lane] = E;
    __syncwarp();

    // ---- forward: packed products of (1 + E_j e^{delta w}) over j ----
    const float2* t0 = (const float2*)((xk0 == 0.0f) ? g_ewp : g_ewm);
    const float2* t1 = (const float2*)((xk1 == 0.0f) ? g_ewp : g_ewm);
    const float ebf0 = (xk0 == 0.0f) ? eb0.x : eb0.y;
    const float ebf1 = (xk1 == 0.0f) ? eb1.x : eb1.y;
    const unsigned long long* E8 = (const unsigned long long*)sEf[w];

    unsigned long long pA0 = ONE2, pA1 = ONE2;   // dim k0, two j-pair lanes
    unsigned long long pB0 = ONE2, pB1 = ONE2;   // dim k1
    #pragma unroll
    for (int jp = 0; jp < 16; jp += 2) {
        unsigned long long Ea = E8[jp];
        unsigned long long Eb = E8[jp + 1];
        unsigned long long eA0 = ldg2(&t0[jp * DD + k0]);
        unsigned long long eA1 = ldg2(&t0[(jp + 1) * DD + k0]);
        unsigned long long eB0 = ldg2(&t1[jp * DD + k1]);
        unsigned long long eB1 = ldg2(&t1[(jp + 1) * DD + k1]);
        unsigned long long f;
        FMA2(f, Ea, eA0, ONE2);  MUL2(pA0, pA0, f);
        FMA2(f, Eb, eA1, ONE2);  MUL2(pA1, pA1, f);
        FMA2(f, Ea, eB0, ONE2);  MUL2(pB0, pB0, f);
        FMA2(f, Eb, eB1, ONE2);  MUL2(pB1, pB1, f);
    }
    float2 a0 = unpack2(pA0), a1 = unpack2(pA1);
    float2 b0 = unpack2(pB0), b1 = unpack2(pB1);
    float ek0 = ebf0 * sqrtf((a0.x * a0.y) * (a1.x * a1.y));
    float ek1 = ebf1 * sqrtf((b0.x * b0.y) * (b1.x * b1.y));

    // gumbel-max in exp domain: argmax(l+g) == argmax(ek / z); keys > 0
    float key0 = ek0 / z0;
    float key1 = ek1 / z1;

    float key; int ki;
    if (key0 >= key1) { key = key0; ki = k0; } else { key = key1; ki = k1; }

    // warp sum (5 shfl) + warp argmax (redux + ballot + 1 shfl)
    float s = ek0 + ek1;
    #pragma unroll
    for (int off = 16; off; off >>= 1) s += __shfl_xor_sync(0xffffffffu, s, off);
    unsigned km   = fmono(key);
    unsigned wmax = __reduce_max_sync(0xffffffffu, km);
    unsigned ball = __ballot_sync(0xffffffffu, km == wmax);
    int      wki  = __shfl_sync(0xffffffffu, ki, __ffs(ball) - 1);
    if (lane == 0) { sredf[w] = s; sredk[w] = make_uint2(wmax, (unsigned)wki); }
    __syncthreads();                           // B2 (genuine combine)

    // ---- every thread combines 4 warp partials via broadcast LDS ----
    float Sf;
    int   kstar;
    {
        Sf = (sredf[0] + sredf[1]) + (sredf[2] + sredf[3]);
        uint2 c0 = sredk[0], c1 = sredk[1], c2 = sredk[2], c3 = sredk[3];
        uint2 mA = (c1.x > c0.x || (c1.x == c0.x && c1.y < c0.y)) ? c1 : c0;
        uint2 mB = (c3.x > c2.x || (c3.x == c2.x && c3.y < c2.y)) ? c3 : c2;
        uint2 mm = (mB.x > mA.x || (mB.x == mA.x && mB.y < mA.y)) ? mB : mA;
        kstar = (int)mm.y;
    }

    // ---- rank-1 update, per-warp redundant: coalesced row read; R in register ----
    float Rt;
    {
        float xks = xs[kstar];                 // visible: written pre-B2
        const float* rowt = (xks == 0.0f) ? g_ewpR : g_ewmR;
        float mj  = __ldg(&rowt[kstar * HH + lane]);
        float E2  = E * mj;
        sE2[w][lane] = E2;
        float rr = (1.f + E2) / (1.f + E);
        #pragma unroll
        for (int off = 16; off; off >>= 1) rr *= __shfl_xor_sync(0xffffffffu, rr, off);
        Rt = rr;
        __syncwarp();
    }

    // ---- reverse pass at x_delta: tables flip only for the kstar dim ----
    const float2* t0r = (k0 == kstar) ? ((xk0 == 0.0f) ? (const float2*)g_ewm : (const float2*)g_ewp) : t0;
    const float2* t1r = (k1 == kstar) ? ((xk1 == 0.0f) ? (const float2*)g_ewm : (const float2*)g_ewp) : t1;
    const float ebr0 = (k0 == kstar) ? ((xk0 == 0.0f) ? eb0.y : eb0.x) : ebf0;
    const float ebr1 = (k1 == kstar) ? ((xk1 == 0.0f) ? eb1.y : eb1.x) : ebf1;
    const unsigned long long* F8 = (const unsigned long long*)sE2[w];

    unsigned long long qA0 = ONE2, qA1 = ONE2;
    unsigned long long qB0 = ONE2, qB1 = ONE2;
    #pragma unroll
    for (int jp = 0; jp < 16; jp += 2) {
        unsigned long long Ea = F8[jp];
        unsigned long long Eb = F8[jp + 1];
        unsigned long long eA0 = ldg2(&t0r[jp * DD + k0]);
        unsigned long long eA1 = ldg2(&t0r[(jp + 1) * DD + k0]);
        unsigned long long eB0 = ldg2(&t1r[jp * DD + k1]);
        unsigned long long eB1 = ldg2(&t1r[(jp + 1) * DD + k1]);
        unsigned long long f;
        FMA2(f, Ea, eA0, ONE2);  MUL2(qA0, qA0, f);
        FMA2(f, Eb, eA1, ONE2);  MUL2(qA1, qA1, f);
        FMA2(f, Ea, eB0, ONE2);  MUL2(qB0, qB0, f);
        FMA2(f, Eb, eB1, ONE2);  MUL2(qB1, qB1, f);
    }
    float2 c0v = unpack2(qA0), c1v = unpack2(qA1);
    float2 d0v = unpack2(qB0), d1v = unpack2(qB1);
    float er0 = ebr0 * sqrtf((c0v.x * c0v.y) * (c1v.x * c1v.y));
    float er1 = ebr1 * sqrtf((d0v.x * d0v.y) * (d1v.x * d1v.y));

    float s2 = er0 + er1;
    #pragma unroll
    for (int off = 16; off; off >>= 1) s2 += __shfl_xor_sync(0xffffffffu, s2, off);
    if (lane == 0) sredf[w] = s2;
    __syncthreads();                           // B4 (genuine combine)

    float Sr = (sredf[0] + sredf[1]) + (sredf[2] + sredf[3]);

    // ---- accept: Zf/Zr = sqrt(R) * Sf / Sr > u ----
    bool accv = sqrtf(Rt) * Sf > au * Sr;
    out[row * DD + k0] = (k0 == kstar && accv) ? (1.f - xk0) : xk0;
    out[row * DD + k1] = (k1 == kstar && accv) ? (1.f - xk1) : xk1;
}

extern "C" void kernel_launch(void* const* d_in, const int* in_sizes, int n_in,
                              void* d_out, int out_size) {
    const float* x   = (const float*)d_in[0];
    const float* W   = (const float*)d_in[1];
    const float* b   = (const float*)d_in[2];
    const float* c   = (const float*)d_in[3];
    const float* gum = (const float*)d_in[4];
    const float* acc = (const float*)d_in[5];
    float* out = (float*)d_out;

    prep_kernel<<<8 + BB / 8, 256>>>(x, W, b, c);

    cudaLaunchConfig_t cfg = {};
    cfg.gridDim  = dim3(BB, 1, 1);
    cfg.blockDim = dim3(128, 1, 1);
    cfg.dynamicSmemBytes = 0;
    cfg.stream = 0;
    cudaLaunchAttribute attrs[1];
    attrs[0].id = cudaLaunchAttributeProgrammaticStreamSerialization;
    attrs[0].val.programmaticStreamSerializationAllowed = 1;
    cfg.attrs = attrs;
    cfg.numAttrs = 1;
    cudaLaunchKernelEx(&cfg, gwg_kernel, x, gum, acc, out);
}